// round 5
// baseline (speedup 1.0000x reference)
#include <cuda_runtime.h>
#include <cuda_bf16.h>
#include <mma.h>
#include <cmath>

using namespace nvcuda;
typedef __nv_bfloat16 bf16;

// ---------------- problem constants ----------------
#define NWIN   8192
#define TTOK   401408
#define HWI    224
#define HWSQ   50176
#define DIMC   192

__device__ __forceinline__ float tf32r(float v) {
    float r;
    asm("cvt.rna.tf32.f32 %0, %1;" : "=f"(r) : "f"(v));
    return r;
}

// scratch (allocation-free static device arrays)
__device__ float g_h1  [(size_t)TTOK * DIMC];   // x + attn branch (fp32)
__device__ bf16  g_h1n [(size_t)TTOK * DIMC];   // LN2(h1) in bf16 (MLP input)
__device__ float g_qkvw_t[192 * 576];           // tf32-rounded
__device__ float g_projw_t[192 * 192];          // tf32-rounded
__device__ bf16  g_fc1w_b [192 * 768];          // bf16
__device__ bf16  g_fc2w_b [768 * 192];          // bf16
__device__ float g_bias   [6 * 49 * 49];        // rpb[relidx[r,j]*6+h]

// tf32 fragments (attention path)
typedef wmma::fragment<wmma::matrix_a,16,16,8,wmma::precision::tf32,wmma::row_major> FragA;
typedef wmma::fragment<wmma::matrix_b,16,16,8,wmma::precision::tf32,wmma::row_major> FragB;
typedef wmma::fragment<wmma::matrix_b,16,16,8,wmma::precision::tf32,wmma::col_major> FragBT;
typedef wmma::fragment<wmma::accumulator,16,16,8,float> FragC;
// bf16 fragments (MLP path)
typedef wmma::fragment<wmma::matrix_a,16,16,16,bf16,wmma::row_major> FragAb;
typedef wmma::fragment<wmma::matrix_b,16,16,16,bf16,wmma::row_major> FragBb;
typedef wmma::fragment<wmma::accumulator,16,16,16,float> FragCb;

// ---------------- prelude ----------------
#define W_QKV 110592
#define W_PRJ  36864
#define W_FC1 147456
#define W_FC2 147456
#define N_BIAS 14406
#define PRE_TOT (W_QKV + W_PRJ + W_FC1 + W_FC2 + N_BIAS)

__global__ void prelude(const float* __restrict__ qkvw, const float* __restrict__ projw,
                        const float* __restrict__ fc1w, const float* __restrict__ fc2w,
                        const float* __restrict__ rpb,  const int* __restrict__ relidx)
{
    int i = blockIdx.x * blockDim.x + threadIdx.x;
    if (i < W_QKV) { g_qkvw_t[i] = tf32r(qkvw[i]); return; }
    i -= W_QKV;
    if (i < W_PRJ) { g_projw_t[i] = tf32r(projw[i]); return; }
    i -= W_PRJ;
    if (i < W_FC1) { g_fc1w_b[i] = __float2bfloat16(fc1w[i]); return; }
    i -= W_FC1;
    if (i < W_FC2) { g_fc2w_b[i] = __float2bfloat16(fc2w[i]); return; }
    i -= W_FC2;
    if (i < N_BIAS) {
        int h = i / 2401, rj = i - h * 2401;
        g_bias[i] = rpb[relidx[rj] * 6 + h];
    }
}

// ============================================================================
// Kernel 1: per-window (512 threads, 16 warps), tf32 numerics as round 4.
// smem floats: xs[64][196]@0  qkv[64][580]@12544  sc[64][68]@49664
// ============================================================================
#define XS_LD 196
#define QK_LD 580
#define SC_LD 68
#define ATTN_SMEM 216064

__global__ void __launch_bounds__(512, 1)
attn_kernel(const float* __restrict__ x,
            const float* __restrict__ ln1w, const float* __restrict__ ln1b,
            const float* __restrict__ qkvb,
            const float* __restrict__ projb,
            const float* __restrict__ ln2w, const float* __restrict__ ln2b)
{
    extern __shared__ float sm[];
    float* xs  = sm;
    float* qkv = sm + 12544;
    float* sc  = sm + 49664;

    const int tid  = threadIdx.x;
    const int wid  = tid >> 5;
    const int lane = tid & 31;

    const int win = blockIdx.x;
    const int b   = win >> 10;
    const int wh  = (win >> 5) & 31;
    const int ww  = win & 31;
    const float* xb = x + (size_t)b * DIMC * HWSQ;

    for (int i = 49 * XS_LD + tid; i < 64 * XS_LD; i += 512) xs[i] = 0.f;
    for (int idx = tid; idx < DIMC * 49; idx += 512) {
        int c = idx / 49, r = idx - c * 49;
        int i = r / 7, j = r - i * 7;
        xs[r * XS_LD + c] = xb[(size_t)c * HWSQ + (wh * 7 + i) * HWI + (ww * 7 + j)];
    }
    __syncthreads();

    // LN1 -> tf32-rounded
    for (int r = wid; r < 49; r += 16) {
        float v[6]; float s = 0.f;
#pragma unroll
        for (int q = 0; q < 6; q++) { v[q] = xs[r * XS_LD + lane + q * 32]; s += v[q]; }
#pragma unroll
        for (int o = 16; o; o >>= 1) s += __shfl_xor_sync(~0u, s, o);
        float mu = s * (1.f / 192.f);
        float vs = 0.f;
#pragma unroll
        for (int q = 0; q < 6; q++) { float d = v[q] - mu; vs += d * d; }
#pragma unroll
        for (int o = 16; o; o >>= 1) vs += __shfl_xor_sync(~0u, vs, o);
        float rs = rsqrtf(vs * (1.f / 192.f) + 1e-5f);
#pragma unroll
        for (int q = 0; q < 6; q++) {
            int c = lane + q * 32;
            xs[r * XS_LD + c] = tf32r((v[q] - mu) * rs * ln1w[c] + ln1b[c]);
        }
    }
    __syncthreads();

    // ---- QKV GEMM: B-stationary. warp w owns cts {w, w+16}; leftover 16
    //      tiles (cts 32..35 x rt 0..3) one per warp. B loaded once per ct. ----
#pragma unroll
    for (int cc = 0; cc < 2; cc++) {
        const int ct = wid + 16 * cc;
        FragC acc[4];
#pragma unroll
        for (int j = 0; j < 4; j++) wmma::fill_fragment(acc[j], 0.f);
        FragB bfr[2];
        wmma::load_matrix_sync(bfr[0], g_qkvw_t + ct * 16, 576);
#pragma unroll
        for (int k = 0; k < 24; k++) {
            if (k < 23)
                wmma::load_matrix_sync(bfr[(k + 1) & 1], g_qkvw_t + (size_t)(k + 1) * 8 * 576 + ct * 16, 576);
#pragma unroll
            for (int j = 0; j < 4; j++) {
                FragA af; wmma::load_matrix_sync(af, xs + j * 16 * XS_LD + k * 8, XS_LD);
                wmma::mma_sync(acc[j], af, bfr[k & 1], acc[j]);
            }
        }
#pragma unroll
        for (int j = 0; j < 4; j++)
            wmma::store_matrix_sync(qkv + j * 16 * QK_LD + ct * 16, acc[j], QK_LD, wmma::mem_row_major);
    }
    {   // leftover: warp w -> tile (rt = w>>2, ct = 32 + (w&3))
        const int ct = 32 + (wid & 3), rt = wid >> 2;
        FragC acc; wmma::fill_fragment(acc, 0.f);
        FragB bfr[2];
        wmma::load_matrix_sync(bfr[0], g_qkvw_t + ct * 16, 576);
#pragma unroll
        for (int k = 0; k < 24; k++) {
            if (k < 23)
                wmma::load_matrix_sync(bfr[(k + 1) & 1], g_qkvw_t + (size_t)(k + 1) * 8 * 576 + ct * 16, 576);
            FragA af; wmma::load_matrix_sync(af, xs + rt * 16 * XS_LD + k * 8, XS_LD);
            wmma::mma_sync(acc, af, bfr[k & 1], acc);
        }
        wmma::store_matrix_sync(qkv + rt * 16 * QK_LD + ct * 16, acc, QK_LD, wmma::mem_row_major);
    }
    __syncthreads();
    // epilogue: bias, scale q, tf32-round (rows<49; pad rows stay 0)
    const float scale = 0.17677669529663687f;
    for (int idx = tid; idx < 49 * 576; idx += 512) {
        int r = idx / 576, c = idx - r * 576;
        float v = qkv[r * QK_LD + c] + qkvb[c];
        if (c < 192) v *= scale;
        qkv[r * QK_LD + c] = tf32r(v);
    }
    __syncthreads();

    // ---- attention: one head per iteration ----
    for (int h = 0; h < 6; h++) {
        {   // scores: 16 tiles, one per warp
            int rt = wid >> 2, ct = wid & 3;
            FragC acc; wmma::fill_fragment(acc, 0.f);
#pragma unroll
            for (int k = 0; k < 4; k++) {
                FragA af; wmma::load_matrix_sync(af, qkv + rt * 16 * QK_LD + h * 32 + k * 8, QK_LD);
                FragBT bf; wmma::load_matrix_sync(bf, qkv + ct * 16 * QK_LD + 192 + h * 32 + k * 8, QK_LD);
                wmma::mma_sync(acc, af, bf, acc);
            }
            wmma::store_matrix_sync(sc + rt * 16 * SC_LD + ct * 16, acc, SC_LD, wmma::mem_row_major);
        }
        __syncthreads();

        const float* bh = g_bias + h * 2401;
        for (int r = wid; r < 49; r += 16) {
            float* srow = sc + r * SC_LD;
            int j0 = lane, j1 = lane + 32;
            float v0 = srow[j0] + bh[r * 49 + j0];
            float v1 = (j1 < 49) ? srow[j1] + bh[r * 49 + j1] : -1e30f;
            float m = fmaxf(v0, v1);
#pragma unroll
            for (int o = 16; o; o >>= 1) m = fmaxf(m, __shfl_xor_sync(~0u, m, o));
            float e0 = expf(v0 - m);
            float e1 = (j1 < 49) ? expf(v1 - m) : 0.f;
            float s = e0 + e1;
#pragma unroll
            for (int o = 16; o; o >>= 1) s += __shfl_xor_sync(~0u, s, o);
            float inv = 1.f / s;
            srow[j0] = tf32r(e0 * inv);
            if (j1 < 49) srow[j1] = tf32r(e1 * inv);
        }
        __syncthreads();

        if (wid < 8) { // PV: 8 tiles
            int rt = wid >> 1, ct = wid & 1;
            FragC acc; wmma::fill_fragment(acc, 0.f);
#pragma unroll
            for (int k = 0; k < 8; k++) {
                FragA af; wmma::load_matrix_sync(af, sc + rt * 16 * SC_LD + k * 8, SC_LD);
                FragB bf; wmma::load_matrix_sync(bf, qkv + (size_t)k * 8 * QK_LD + 384 + h * 32 + ct * 16, QK_LD);
                wmma::mma_sync(acc, af, bf, acc);
            }
            wmma::store_matrix_sync(xs + rt * 16 * XS_LD + h * 32 + ct * 16, acc, XS_LD, wmma::mem_row_major);
        }
        __syncthreads();
    }

    // tf32-round attn output (proj A operand)
    for (int idx = tid; idx < 49 * 192; idx += 512) {
        int r = idx / 192, c = idx - r * 192;
        xs[r * XS_LD + c] = tf32r(xs[r * XS_LD + c]);
    }
    __syncthreads();

    // ---- proj GEMM: B-stationary, warps 0..11 own one ct each ----
    if (wid < 12) {
        const int ct = wid;
        FragC acc[4];
#pragma unroll
        for (int j = 0; j < 4; j++) wmma::fill_fragment(acc[j], 0.f);
        FragB bfr[2];
        wmma::load_matrix_sync(bfr[0], g_projw_t + ct * 16, 192);
#pragma unroll
        for (int k = 0; k < 24; k++) {
            if (k < 23)
                wmma::load_matrix_sync(bfr[(k + 1) & 1], g_projw_t + (size_t)(k + 1) * 8 * 192 + ct * 16, 192);
#pragma unroll
            for (int j = 0; j < 4; j++) {
                FragA af; wmma::load_matrix_sync(af, xs + j * 16 * XS_LD + k * 8, XS_LD);
                wmma::mma_sync(acc[j], af, bfr[k & 1], acc[j]);
            }
        }
#pragma unroll
        for (int j = 0; j < 4; j++)
            wmma::store_matrix_sync(qkv + j * 16 * XS_LD + ct * 16, acc[j], XS_LD, wmma::mem_row_major);
    }
    __syncthreads();

    // residual: qkv(ld XS_LD) += x + projb
    for (int idx = tid; idx < DIMC * 49; idx += 512) {
        int c = idx / 49, r = idx - c * 49;
        int i = r / 7, j = r - i * 7;
        float xv = xb[(size_t)c * HWSQ + (wh * 7 + i) * HWI + (ww * 7 + j)];
        qkv[r * XS_LD + c] += xv + projb[c];
    }
    __syncthreads();

    // LN2 + write h1 (fp32) / h1n (bf16)
    size_t base = (size_t)win * 49 * DIMC;
    for (int r = wid; r < 49; r += 16) {
        float v[6]; float s = 0.f;
#pragma unroll
        for (int q = 0; q < 6; q++) { v[q] = qkv[r * XS_LD + lane + q * 32]; s += v[q]; }
#pragma unroll
        for (int o = 16; o; o >>= 1) s += __shfl_xor_sync(~0u, s, o);
        float mu = s * (1.f / 192.f);
        float vs = 0.f;
#pragma unroll
        for (int q = 0; q < 6; q++) { float d = v[q] - mu; vs += d * d; }
#pragma unroll
        for (int o = 16; o; o >>= 1) vs += __shfl_xor_sync(~0u, vs, o);
        float rs = rsqrtf(vs * (1.f / 192.f) + 1e-5f);
#pragma unroll
        for (int q = 0; q < 6; q++) {
            int c = lane + q * 32;
            g_h1 [base + r * DIMC + c] = v[q];
            g_h1n[base + r * DIMC + c] = __float2bfloat16((v[q] - mu) * rs * ln2w[c] + ln2b[c]);
        }
    }
}

// ============================================================================
// Kernel 2 (384 threads = 12 warps, 2 CTAs/SM): bf16 MLP, 64 tokens/CTA,
// 4 K-chunks of 192. B-stationary: warp w owns output col tile ct = w.
// GEMM1: two rt-half passes (2 accs). GEMM2: 4 register accs across chunks.
// smem: as bf16[64][200]@0 (25600B); mid f32[64][196]@25600 (50176B);
//       midb bf16[64][200]@75776 (25600B); total 101376
// ============================================================================
#define AS_LD 200
#define MD_LD 196
#define MLP_SMEM 101376
#define MTH 384

__global__ void __launch_bounds__(MTH, 2)
mlp_kernel(const float* __restrict__ fc1b, const float* __restrict__ fc2b,
           float* __restrict__ out)
{
    extern __shared__ char smc[];
    bf16*  as   = (bf16*)smc;
    float* mid  = (float*)(smc + 25600);
    bf16*  midb = (bf16*)(smc + 75776);

    const int tid = threadIdx.x;
    const int wid = tid >> 5;      // 0..11
    const int t0  = blockIdx.x * 64;

    // load h1n tile (uint4 = 8 bf16, coalesced)
    {
        const uint4* src = (const uint4*)g_h1n;
        uint4* dst = (uint4*)as;
        for (int idx = tid; idx < 64 * 24; idx += MTH) {
            int r = idx / 24, c = idx - r * 24;
            dst[r * 25 + c] = src[(size_t)(t0 + r) * 24 + c];
        }
    }
    __syncthreads();

    FragCb acc2[4];
#pragma unroll
    for (int j = 0; j < 4; j++) wmma::fill_fragment(acc2[j], 0.f);

    const int ct = wid;   // each warp owns one of 12 col tiles

    for (int chunk = 0; chunk < 4; chunk++) {
        // GEMM1: [64,192]x[192,192] bf16; two rt-half passes, B once per pass
#pragma unroll
        for (int rh = 0; rh < 2; rh++) {
            FragCb acc[2];
#pragma unroll
            for (int j = 0; j < 2; j++) wmma::fill_fragment(acc[j], 0.f);
            FragBb bfr[2];
            wmma::load_matrix_sync(bfr[0], g_fc1w_b + (size_t)chunk * 192 + ct * 16, 768);
#pragma unroll
            for (int k = 0; k < 12; k++) {
                if (k < 11)
                    wmma::load_matrix_sync(bfr[(k + 1) & 1],
                        g_fc1w_b + (size_t)(k + 1) * 16 * 768 + chunk * 192 + ct * 16, 768);
#pragma unroll
                for (int j = 0; j < 2; j++) {
                    FragAb af;
                    wmma::load_matrix_sync(af, as + (rh * 2 + j) * 16 * AS_LD + k * 16, AS_LD);
                    wmma::mma_sync(acc[j], af, bfr[k & 1], acc[j]);
                }
            }
#pragma unroll
            for (int j = 0; j < 2; j++)
                wmma::store_matrix_sync(mid + (rh * 2 + j) * 16 * MD_LD + ct * 16, acc[j], MD_LD, wmma::mem_row_major);
        }
        __syncthreads();

        // bias + exact GELU -> midb bf16
        for (int idx = tid; idx < 64 * 192; idx += MTH) {
            int r = idx / 192, c = idx - r * 192;
            float v = mid[r * MD_LD + c] + fc1b[chunk * 192 + c];
            midb[r * AS_LD + c] = __float2bfloat16(0.5f * v * (1.f + erff(v * 0.70710678118654752f)));
        }
        __syncthreads();

        // GEMM2 partial: B once per k, 4 rt accs held in registers across chunks
        {
            FragBb bfr[2];
            wmma::load_matrix_sync(bfr[0], g_fc2w_b + (size_t)chunk * 192 * 192 + ct * 16, 192);
#pragma unroll
            for (int k = 0; k < 12; k++) {
                if (k < 11)
                    wmma::load_matrix_sync(bfr[(k + 1) & 1],
                        g_fc2w_b + (size_t)(chunk * 192 + (k + 1) * 16) * 192 + ct * 16, 192);
#pragma unroll
                for (int j = 0; j < 4; j++) {
                    FragAb af;
                    wmma::load_matrix_sync(af, midb + j * 16 * AS_LD + k * 16, AS_LD);
                    wmma::mma_sync(acc2[j], af, bfr[k & 1], acc2[j]);
                }
            }
        }
        __syncthreads();
    }

    // store MLP output to mid
#pragma unroll
    for (int j = 0; j < 4; j++)
        wmma::store_matrix_sync(mid + j * 16 * MD_LD + ct * 16, acc2[j], MD_LD, wmma::mem_row_major);
    __syncthreads();

    // residual + bias + scatter to NCHW (single pass)
    for (int idx = tid; idx < 64 * 192; idx += MTH) {
        int r = idx & 63;
        int c = idx >> 6;
        int t = t0 + r;
        int win = t / 49; int pos = t - win * 49;
        int b  = win >> 10;
        int wh = (win >> 5) & 31;
        int ww = win & 31;
        int pi = pos / 7;
        int hh = wh * 7 + pi;
        int wx = ww * 7 + (pos - pi * 7);
        out[((size_t)(b * DIMC + c)) * HWSQ + hh * HWI + wx] =
            mid[r * MD_LD + c] + g_h1[(size_t)t * 192 + c] + fc2b[c];
    }
}

// ============================================================================
extern "C" void kernel_launch(void* const* d_in, const int* in_sizes, int n_in,
                              void* d_out, int out_size)
{
    (void)in_sizes; (void)n_in; (void)out_size;
    const float* x     = (const float*)d_in[0];
    const float* ln1w  = (const float*)d_in[1];
    const float* ln1b  = (const float*)d_in[2];
    const float* qkvw  = (const float*)d_in[3];
    const float* qkvb  = (const float*)d_in[4];
    const float* projw = (const float*)d_in[5];
    const float* projb = (const float*)d_in[6];
    const float* rpb   = (const float*)d_in[7];
    const float* ln2w  = (const float*)d_in[8];
    const float* ln2b  = (const float*)d_in[9];
    const float* fc1w  = (const float*)d_in[10];
    const float* fc1b  = (const float*)d_in[11];
    const float* fc2w  = (const float*)d_in[12];
    const float* fc2b  = (const float*)d_in[13];
    const int*   ridx  = (const int*)  d_in[14];
    float* out = (float*)d_out;

    cudaFuncSetAttribute(attn_kernel, cudaFuncAttributeMaxDynamicSharedMemorySize, ATTN_SMEM);
    cudaFuncSetAttribute(mlp_kernel,  cudaFuncAttributeMaxDynamicSharedMemorySize, MLP_SMEM);

    prelude<<<(PRE_TOT + 511) / 512, 512>>>(qkvw, projw, fc1w, fc2w, rpb, ridx);

    attn_kernel<<<NWIN, 512, ATTN_SMEM>>>(x, ln1w, ln1b, qkvb, projb, ln2w, ln2b);

    mlp_kernel<<<TTOK / 64, MTH, MLP_SMEM>>>(fc1b, fc2b, out);
}

// round 6
// speedup vs baseline: 1.2018x; 1.2018x over previous
#include <cuda_runtime.h>
#include <cuda_bf16.h>
#include <mma.h>
#include <cmath>

using namespace nvcuda;
typedef __nv_bfloat16 bf16;

// ---------------- problem constants ----------------
#define NWIN   8192
#define TTOK   401408
#define HWI    224
#define HWSQ   50176
#define DIMC   192

__device__ __forceinline__ float tf32r(float v) {
    float r;
    asm("cvt.rna.tf32.f32 %0, %1;" : "=f"(r) : "f"(v));
    return r;
}

// scratch (allocation-free static device arrays)
__device__ float g_h1  [(size_t)TTOK * DIMC];   // x + attn branch (fp32)
__device__ bf16  g_h1n [(size_t)TTOK * DIMC];   // LN2(h1) in bf16 (MLP input)
__device__ float g_qkvw_t[192 * 576];           // tf32-rounded
__device__ float g_projw_t[192 * 192];          // tf32-rounded
__device__ bf16  g_fc1w_b [192 * 768];          // bf16
__device__ bf16  g_fc2w_b [768 * 192];          // bf16
__device__ float g_bias   [6 * 49 * 49];        // rpb[relidx[r,j]*6+h]

// tf32 fragments (attention path)
typedef wmma::fragment<wmma::matrix_a,16,16,8,wmma::precision::tf32,wmma::row_major> FragA;
typedef wmma::fragment<wmma::matrix_b,16,16,8,wmma::precision::tf32,wmma::row_major> FragB;
typedef wmma::fragment<wmma::matrix_b,16,16,8,wmma::precision::tf32,wmma::col_major> FragBT;
typedef wmma::fragment<wmma::accumulator,16,16,8,float> FragC;
// bf16 fragments (MLP path)
typedef wmma::fragment<wmma::matrix_a,16,16,16,bf16,wmma::row_major> FragAb;
typedef wmma::fragment<wmma::matrix_b,16,16,16,bf16,wmma::row_major> FragBb;
typedef wmma::fragment<wmma::accumulator,16,16,16,float> FragCb;

// ---------------- prelude ----------------
#define W_QKV 110592
#define W_PRJ  36864
#define W_FC1 147456
#define W_FC2 147456
#define N_BIAS 14406
#define PRE_TOT (W_QKV + W_PRJ + W_FC1 + W_FC2 + N_BIAS)

__global__ void prelude(const float* __restrict__ qkvw, const float* __restrict__ projw,
                        const float* __restrict__ fc1w, const float* __restrict__ fc2w,
                        const float* __restrict__ rpb,  const int* __restrict__ relidx)
{
    int i = blockIdx.x * blockDim.x + threadIdx.x;
    if (i < W_QKV) { g_qkvw_t[i] = tf32r(qkvw[i]); return; }
    i -= W_QKV;
    if (i < W_PRJ) { g_projw_t[i] = tf32r(projw[i]); return; }
    i -= W_PRJ;
    if (i < W_FC1) { g_fc1w_b[i] = __float2bfloat16(fc1w[i]); return; }
    i -= W_FC1;
    if (i < W_FC2) { g_fc2w_b[i] = __float2bfloat16(fc2w[i]); return; }
    i -= W_FC2;
    if (i < N_BIAS) {
        int h = i / 2401, rj = i - h * 2401;
        g_bias[i] = rpb[relidx[rj] * 6 + h];
    }
}

// ============================================================================
// Kernel 1: per-window (512 threads, 16 warps), numerics identical to round 4.
// smem floats: xs[64][196]@0  qkv[64][580]@12544  sc[64][68]@49664
// Attention head-loop uses 4 independent 4-warp groups (one per rt block)
// synchronized by named barriers only.
// ============================================================================
#define XS_LD 196
#define QK_LD 580
#define SC_LD 68
#define ATTN_SMEM 216064

__device__ __forceinline__ void group_bar(int barid) {
    asm volatile("bar.sync %0, %1;" :: "r"(barid), "r"(128) : "memory");
}

__global__ void __launch_bounds__(512, 1)
attn_kernel(const float* __restrict__ x,
            const float* __restrict__ ln1w, const float* __restrict__ ln1b,
            const float* __restrict__ qkvb,
            const float* __restrict__ projb,
            const float* __restrict__ ln2w, const float* __restrict__ ln2b)
{
    extern __shared__ float sm[];
    float* xs  = sm;
    float* qkv = sm + 12544;
    float* sc  = sm + 49664;

    const int tid  = threadIdx.x;
    const int wid  = tid >> 5;
    const int lane = tid & 31;

    const int win = blockIdx.x;
    const int b   = win >> 10;
    const int wh  = (win >> 5) & 31;
    const int ww  = win & 31;
    const float* xb = x + (size_t)b * DIMC * HWSQ;

    for (int i = 49 * XS_LD + tid; i < 64 * XS_LD; i += 512) xs[i] = 0.f;
    for (int idx = tid; idx < DIMC * 49; idx += 512) {
        int c = idx / 49, r = idx - c * 49;
        int i = r / 7, j = r - i * 7;
        xs[r * XS_LD + c] = xb[(size_t)c * HWSQ + (wh * 7 + i) * HWI + (ww * 7 + j)];
    }
    __syncthreads();

    // LN1 -> tf32-rounded
    for (int r = wid; r < 49; r += 16) {
        float v[6]; float s = 0.f;
#pragma unroll
        for (int q = 0; q < 6; q++) { v[q] = xs[r * XS_LD + lane + q * 32]; s += v[q]; }
#pragma unroll
        for (int o = 16; o; o >>= 1) s += __shfl_xor_sync(~0u, s, o);
        float mu = s * (1.f / 192.f);
        float vs = 0.f;
#pragma unroll
        for (int q = 0; q < 6; q++) { float d = v[q] - mu; vs += d * d; }
#pragma unroll
        for (int o = 16; o; o >>= 1) vs += __shfl_xor_sync(~0u, vs, o);
        float rs = rsqrtf(vs * (1.f / 192.f) + 1e-5f);
#pragma unroll
        for (int q = 0; q < 6; q++) {
            int c = lane + q * 32;
            xs[r * XS_LD + c] = tf32r((v[q] - mu) * rs * ln1w[c] + ln1b[c]);
        }
    }
    __syncthreads();

    // ---- QKV GEMM: k-outer, 9 accumulators (round-4 structure) ----
    {
        const int rt = wid & 3, ctb = wid >> 2;
        FragC acc[9];
#pragma unroll
        for (int j = 0; j < 9; j++) wmma::fill_fragment(acc[j], 0.f);
        for (int k = 0; k < 24; k++) {
            FragA af; wmma::load_matrix_sync(af, xs + rt * 16 * XS_LD + k * 8, XS_LD);
#pragma unroll
            for (int j = 0; j < 9; j++) {
                FragB bf;
                wmma::load_matrix_sync(bf, g_qkvw_t + (size_t)k * 8 * 576 + (ctb + 4 * j) * 16, 576);
                wmma::mma_sync(acc[j], af, bf, acc[j]);
            }
        }
#pragma unroll
        for (int j = 0; j < 9; j++)
            wmma::store_matrix_sync(qkv + rt * 16 * QK_LD + (ctb + 4 * j) * 16, acc[j], QK_LD, wmma::mem_row_major);
    }
    __syncthreads();
    // epilogue: bias, scale q, tf32-round (rows<49; pad rows stay 0)
    const float scale = 0.17677669529663687f;
    for (int idx = tid; idx < 49 * 576; idx += 512) {
        int r = idx / 576, c = idx - r * 576;
        float v = qkv[r * QK_LD + c] + qkvb[c];
        if (c < 192) v *= scale;
        qkv[r * QK_LD + c] = tf32r(v);
    }
    __syncthreads();

    // ---- attention: 4 independent 4-warp groups, one rt block each.
    //      qkv is read-only here; sc rows are group-private; PV writes
    //      group-private xs rows. No __syncthreads in this loop. ----
    {
        const int g  = wid >> 2;     // rt block 0..3
        const int jg = wid & 3;      // warp within group
        const int barid = 1 + g;
        float* scg = sc + g * 16 * SC_LD;

        for (int h = 0; h < 6; h++) {
            {   // scores tile (g, jg)
                FragC acc; wmma::fill_fragment(acc, 0.f);
#pragma unroll
                for (int k = 0; k < 4; k++) {
                    FragA af; wmma::load_matrix_sync(af, qkv + g * 16 * QK_LD + h * 32 + k * 8, QK_LD);
                    FragBT bf; wmma::load_matrix_sync(bf, qkv + jg * 16 * QK_LD + 192 + h * 32 + k * 8, QK_LD);
                    wmma::mma_sync(acc, af, bf, acc);
                }
                wmma::store_matrix_sync(scg + jg * 16, acc, SC_LD, wmma::mem_row_major);
            }
            group_bar(barid);

            // softmax: 4 rows per warp (rows g*16 + jg*4 + i), skip r>=49
            const float* bh = g_bias + h * 2401;
#pragma unroll
            for (int i = 0; i < 4; i++) {
                int r = g * 16 + jg * 4 + i;
                if (r < 49) {
                    float* srow = sc + r * SC_LD;
                    int j0 = lane, j1 = lane + 32;
                    float v0 = srow[j0] + bh[r * 49 + j0];
                    float v1 = (j1 < 49) ? srow[j1] + bh[r * 49 + j1] : -1e30f;
                    float m = fmaxf(v0, v1);
#pragma unroll
                    for (int o = 16; o; o >>= 1) m = fmaxf(m, __shfl_xor_sync(~0u, m, o));
                    float e0 = expf(v0 - m);
                    float e1 = (j1 < 49) ? expf(v1 - m) : 0.f;
                    float s = e0 + e1;
#pragma unroll
                    for (int o = 16; o; o >>= 1) s += __shfl_xor_sync(~0u, s, o);
                    float inv = 1.f / s;
                    srow[j0] = tf32r(e0 * inv);
                    if (j1 < 49) srow[j1] = tf32r(e1 * inv);
                }
            }
            group_bar(barid);

            // PV: warps jg<2 compute tile (g, ct=jg); fold tf32 rounding in
            if (jg < 2) {
                FragC acc; wmma::fill_fragment(acc, 0.f);
#pragma unroll
                for (int k = 0; k < 8; k++) {
                    FragA af; wmma::load_matrix_sync(af, scg + k * 8, SC_LD);
                    FragB bf; wmma::load_matrix_sync(bf, qkv + (size_t)k * 8 * QK_LD + 384 + h * 32 + jg * 16, QK_LD);
                    wmma::mma_sync(acc, af, bf, acc);
                }
                float* dst = xs + g * 16 * XS_LD + h * 32 + jg * 16;
                wmma::store_matrix_sync(dst, acc, XS_LD, wmma::mem_row_major);
                __syncwarp();
#pragma unroll
                for (int e = 0; e < 8; e++) {
                    int el = lane + e * 32;
                    int rr = el >> 4, cc = el & 15;
                    dst[rr * XS_LD + cc] = tf32r(dst[rr * XS_LD + cc]);
                }
            }
            group_bar(barid);   // sc rows reusable for next head
        }
    }
    __syncthreads();

    // ---- proj GEMM: k-outer, 3 accumulators (round-4 structure) ----
    {
        const int rt = wid & 3, ctb = wid >> 2;
        FragC acc[3];
#pragma unroll
        for (int j = 0; j < 3; j++) wmma::fill_fragment(acc[j], 0.f);
        for (int k = 0; k < 24; k++) {
            FragA af; wmma::load_matrix_sync(af, xs + rt * 16 * XS_LD + k * 8, XS_LD);
#pragma unroll
            for (int j = 0; j < 3; j++) {
                FragB bf;
                wmma::load_matrix_sync(bf, g_projw_t + (size_t)k * 8 * 192 + (ctb + 4 * j) * 16, 192);
                wmma::mma_sync(acc[j], af, bf, acc[j]);
            }
        }
#pragma unroll
        for (int j = 0; j < 3; j++)
            wmma::store_matrix_sync(qkv + rt * 16 * XS_LD + (ctb + 4 * j) * 16, acc[j], XS_LD, wmma::mem_row_major);
    }
    __syncthreads();

    // residual: qkv(ld XS_LD) += x + projb
    for (int idx = tid; idx < DIMC * 49; idx += 512) {
        int c = idx / 49, r = idx - c * 49;
        int i = r / 7, j = r - i * 7;
        float xv = xb[(size_t)c * HWSQ + (wh * 7 + i) * HWI + (ww * 7 + j)];
        qkv[r * XS_LD + c] += xv + projb[c];
    }
    __syncthreads();

    // LN2 + write h1 (fp32) / h1n (bf16)
    size_t base = (size_t)win * 49 * DIMC;
    for (int r = wid; r < 49; r += 16) {
        float v[6]; float s = 0.f;
#pragma unroll
        for (int q = 0; q < 6; q++) { v[q] = qkv[r * XS_LD + lane + q * 32]; s += v[q]; }
#pragma unroll
        for (int o = 16; o; o >>= 1) s += __shfl_xor_sync(~0u, s, o);
        float mu = s * (1.f / 192.f);
        float vs = 0.f;
#pragma unroll
        for (int q = 0; q < 6; q++) { float d = v[q] - mu; vs += d * d; }
#pragma unroll
        for (int o = 16; o; o >>= 1) vs += __shfl_xor_sync(~0u, vs, o);
        float rs = rsqrtf(vs * (1.f / 192.f) + 1e-5f);
#pragma unroll
        for (int q = 0; q < 6; q++) {
            int c = lane + q * 32;
            g_h1 [base + r * DIMC + c] = v[q];
            g_h1n[base + r * DIMC + c] = __float2bfloat16((v[q] - mu) * rs * ln2w[c] + ln2b[c]);
        }
    }
}

// ============================================================================
// Kernel 2: round-4 MLP, unchanged (256 threads, 2 CTAs/SM, bf16).
// ============================================================================
#define AS_LD 200
#define MD_LD 196
#define MLP_SMEM 101376

__global__ void __launch_bounds__(256, 2)
mlp_kernel(const float* __restrict__ fc1b, const float* __restrict__ fc2b,
           float* __restrict__ out)
{
    extern __shared__ char smc[];
    bf16*  as   = (bf16*)smc;
    float* mid  = (float*)(smc + 25600);
    bf16*  midb = (bf16*)(smc + 75776);

    const int tid = threadIdx.x;
    const int wid = tid >> 5;
    const int t0  = blockIdx.x * 64;
    const int rt  = wid & 3;
    const int ctb = wid >> 2;   // 0 or 1

    {
        const uint4* src = (const uint4*)g_h1n;
        uint4* dst = (uint4*)as;
        for (int idx = tid; idx < 64 * 24; idx += 256) {
            int r = idx / 24, c = idx - r * 24;
            dst[r * 25 + c] = src[(size_t)(t0 + r) * 24 + c];
        }
    }
    __syncthreads();

    FragCb acc2[6];
#pragma unroll
    for (int j = 0; j < 6; j++) wmma::fill_fragment(acc2[j], 0.f);

    for (int chunk = 0; chunk < 4; chunk++) {
#pragma unroll
        for (int g = 0; g < 2; g++) {
            FragCb acc[3];
#pragma unroll
            for (int j = 0; j < 3; j++) wmma::fill_fragment(acc[j], 0.f);
            for (int k = 0; k < 12; k++) {
                FragAb af; wmma::load_matrix_sync(af, as + rt * 16 * AS_LD + k * 16, AS_LD);
#pragma unroll
                for (int j = 0; j < 3; j++) {
                    int ct = ctb + 2 * (3 * g + j);
                    FragBb bf;
                    wmma::load_matrix_sync(bf, g_fc1w_b + (size_t)k * 16 * 768 + chunk * 192 + ct * 16, 768);
                    wmma::mma_sync(acc[j], af, bf, acc[j]);
                }
            }
#pragma unroll
            for (int j = 0; j < 3; j++) {
                int ct = ctb + 2 * (3 * g + j);
                wmma::store_matrix_sync(mid + rt * 16 * MD_LD + ct * 16, acc[j], MD_LD, wmma::mem_row_major);
            }
        }
        __syncthreads();

        for (int idx = tid; idx < 64 * 192; idx += 256) {
            int r = idx / 192, c = idx - r * 192;
            float v = mid[r * MD_LD + c] + fc1b[chunk * 192 + c];
            midb[r * AS_LD + c] = __float2bfloat16(0.5f * v * (1.f + erff(v * 0.70710678118654752f)));
        }
        __syncthreads();

        for (int kk = 0; kk < 12; kk++) {
            FragAb af; wmma::load_matrix_sync(af, midb + rt * 16 * AS_LD + kk * 16, AS_LD);
#pragma unroll
            for (int j = 0; j < 6; j++) {
                int ct = ctb + 2 * j;
                FragBb bf;
                wmma::load_matrix_sync(bf, g_fc2w_b + (size_t)(chunk * 192 + kk * 16) * 192 + ct * 16, 192);
                wmma::mma_sync(acc2[j], af, bf, acc2[j]);
            }
        }
        __syncthreads();
    }

#pragma unroll
    for (int j = 0; j < 6; j++) {
        int ct = ctb + 2 * j;
        wmma::store_matrix_sync(mid + rt * 16 * MD_LD + ct * 16, acc2[j], MD_LD, wmma::mem_row_major);
    }
    __syncthreads();

    for (int idx = tid; idx < 64 * 192; idx += 256) {
        int r = idx & 63;
        int c = idx >> 6;
        int t = t0 + r;
        int win = t / 49; int pos = t - win * 49;
        int b  = win >> 10;
        int wh = (win >> 5) & 31;
        int ww = win & 31;
        int pi = pos / 7;
        int hh = wh * 7 + pi;
        int wx = ww * 7 + (pos - pi * 7);
        out[((size_t)(b * DIMC + c)) * HWSQ + hh * HWI + wx] =
            mid[r * MD_LD + c] + g_h1[(size_t)t * 192 + c] + fc2b[c];
    }
}

// ============================================================================
extern "C" void kernel_launch(void* const* d_in, const int* in_sizes, int n_in,
                              void* d_out, int out_size)
{
    (void)in_sizes; (void)n_in; (void)out_size;
    const float* x     = (const float*)d_in[0];
    const float* ln1w  = (const float*)d_in[1];
    const float* ln1b  = (const float*)d_in[2];
    const float* qkvw  = (const float*)d_in[3];
    const float* qkvb  = (const float*)d_in[4];
    const float* projw = (const float*)d_in[5];
    const float* projb = (const float*)d_in[6];
    const float* rpb   = (const float*)d_in[7];
    const float* ln2w  = (const float*)d_in[8];
    const float* ln2b  = (const float*)d_in[9];
    const float* fc1w  = (const float*)d_in[10];
    const float* fc1b  = (const float*)d_in[11];
    const float* fc2w  = (const float*)d_in[12];
    const float* fc2b  = (const float*)d_in[13];
    const int*   ridx  = (const int*)  d_in[14];
    float* out = (float*)d_out;

    cudaFuncSetAttribute(attn_kernel, cudaFuncAttributeMaxDynamicSharedMemorySize, ATTN_SMEM);
    cudaFuncSetAttribute(mlp_kernel,  cudaFuncAttributeMaxDynamicSharedMemorySize, MLP_SMEM);

    prelude<<<(PRE_TOT + 511) / 512, 512>>>(qkvw, projw, fc1w, fc2w, rpb, ridx);

    attn_kernel<<<NWIN, 512, ATTN_SMEM>>>(x, ln1w, ln1b, qkvb, projb, ln2w, ln2b);

    mlp_kernel<<<TTOK / 64, 256, MLP_SMEM>>>(fc1b, fc2b, out);
}